// round 1
// baseline (speedup 1.0000x reference)
#include <cuda_runtime.h>
#include <math.h>

#define B_ 32
#define N_ 512
#define F_ 32
#define T_ 24
#define K_ 3
#define GC_ 64
#define TC_ 64

// ---------------- scratch (device globals; no allocations allowed) ----------------
__device__ float g_rhs_t[B_ * N_ * T_];          // [b,n,t]
__device__ float g_tmp_bt[B_ * T_ * F_];         // [b,t,f]
__device__ float g_lhs_t[B_ * T_ * N_];          // [b,t,n]
__device__ float g_temp_w[B_ * T_ * T_];         // [b,t,u]
__device__ float g_xtemp[B_ * N_ * F_ * T_];     // [b,n,f,u]
__device__ float g_lhs_s[B_ * N_ * T_];
__device__ float g_rhs_s[B_ * N_ * T_];
__device__ float g_attn[B_ * N_ * N_];           // sigmoid(scores+bias)
__device__ float g_S[B_ * N_ * N_];
__device__ float g_spat[B_ * N_ * N_];
__device__ float g_H[B_ * K_ * N_ * F_ * T_];    // [(b*3+k), n, f*24+t]

// ---------------- K1: rhs_t[b,n,t] = sum_f ta_w3[f] * x[b,n,f,t] ----------------
__global__ void rhs_t_kernel(const float* __restrict__ x, const float* __restrict__ w3) {
    int bn = blockIdx.x;
    __shared__ float row[768];
    const float* xr = x + (size_t)bn * 768;
    for (int i = threadIdx.x; i < 768; i += 128) row[i] = xr[i];
    __syncthreads();
    if (threadIdx.x < 24) {
        int t = threadIdx.x;
        float a = 0.f;
#pragma unroll
        for (int f = 0; f < 32; f++) a += w3[f] * row[f * 24 + t];
        g_rhs_t[bn * 24 + t] = a;
    }
}

// ---------------- K2: tmp_bt[b,t,f] = sum_n ta_w1[n] * x[b,n,f,t] ----------------
__global__ void tmp_bt_kernel(const float* __restrict__ x, const float* __restrict__ w1) {
    int b = blockIdx.x;
    int ft = threadIdx.x;  // f*24+t, 768 threads
    const float* xb = x + (size_t)b * 512 * 768;
    float a = 0.f;
    for (int n = 0; n < 512; n++) a += w1[n] * xb[n * 768 + ft];
    int f = ft / 24, t = ft - f * 24;
    g_tmp_bt[(b * 24 + t) * 32 + f] = a;
}

// ---------------- K3: lhs_t[b,t,n] = sum_f tmp_bt[b,t,f] * ta_w2[f,n] ----------------
__global__ void lhs_t_kernel(const float* __restrict__ w2) {
    int idx = blockIdx.x * blockDim.x + threadIdx.x;  // B*T*N = 393216
    if (idx >= B_ * T_ * N_) return;
    int n = idx & 511;
    int bt = idx >> 9;
    float a = 0.f;
#pragma unroll
    for (int f = 0; f < 32; f++) a += g_tmp_bt[bt * 32 + f] * w2[f * 512 + n];
    g_lhs_t[idx] = a;
}

// ---------------- K4: prod -> sigmoid -> E -> softmax(s)  (block per b, 576 threads) ----------------
__global__ void temporal_attn_kernel(const float* __restrict__ ta_bias,
                                     const float* __restrict__ ta_proj) {
    int b = blockIdx.x;
    int tid = threadIdx.x;       // 0..575
    int t = tid / 24, u = tid - (tid / 24) * 24;
    __shared__ float ssig[576];
    __shared__ float sE[576];

    const float* lrow = g_lhs_t + (b * 24 + t) * 512;
    const float* rcol = g_rhs_t + b * 512 * 24 + u;
    float p = 0.f;
    for (int n = 0; n < 512; n++) p += lrow[n] * rcol[n * 24];
    ssig[t * 24 + u] = 1.f / (1.f + expf(-(p + ta_bias[t * 24 + u])));
    __syncthreads();

    int s = t;
    float e = 0.f;
#pragma unroll
    for (int tt = 0; tt < 24; tt++) e += ta_proj[s * 24 + tt] * ssig[tt * 24 + u];
    sE[s * 24 + u] = e;
    __syncthreads();

    float mx = -1e30f;
#pragma unroll
    for (int ss = 0; ss < 24; ss++) mx = fmaxf(mx, sE[ss * 24 + u]);
    float sum = 0.f;
#pragma unroll
    for (int ss = 0; ss < 24; ss++) sum += expf(sE[ss * 24 + u] - mx);
    g_temp_w[b * 576 + s * 24 + u] = expf(e - mx) / sum;
}

// ---------------- K5: x_temp[b,n,f,u] = sum_t x[b,n,f,t] * temp_w[b,t,u] ----------------
__global__ void xtemp_kernel(const float* __restrict__ x) {
    int idx = blockIdx.x * blockDim.x + threadIdx.x;  // 12582912
    if (idx >= B_ * N_ * F_ * T_) return;
    int u = idx % 24;
    int row = idx / 24;              // b*N*F + n*F + f
    int b = row / (512 * 32);
    const float* xr = x + (size_t)row * 24;
    const float* tw = g_temp_w + b * 576;
    float a = 0.f;
#pragma unroll
    for (int t = 0; t < 24; t++) a += xr[t] * tw[t * 24 + u];
    g_xtemp[idx] = a;
}

// ---------------- K6: spatial pre: lhs_s / rhs_s per (b,n) row of x_temp ----------------
__global__ void spre_kernel(const float* __restrict__ wa, const float* __restrict__ wb,
                            const float* __restrict__ wc) {
    int bn = blockIdx.x;
    __shared__ float row[768];
    __shared__ float st2[32];
    const float* xr = g_xtemp + (size_t)bn * 768;
    for (int i = threadIdx.x; i < 768; i += 128) row[i] = xr[i];
    __syncthreads();
    if (threadIdx.x < 32) {
        int f = threadIdx.x;
        float a = 0.f;
#pragma unroll
        for (int t = 0; t < 24; t++) a += row[f * 24 + t] * wa[t];
        st2[f] = a;
    }
    __syncthreads();
    if (threadIdx.x < 24) {
        int t = threadIdx.x;
        float l = 0.f, r = 0.f;
#pragma unroll
        for (int f = 0; f < 32; f++) {
            l += st2[f] * wb[f * 24 + t];
            r += wc[f] * row[f * 24 + t];
        }
        g_lhs_s[bn * 24 + t] = l;
        g_rhs_s[bn * 24 + t] = r;
    }
}

// ---------------- K7: attn[b,n,m] = sigmoid(sum_t lhs_s[b,n,t]*rhs_s[b,m,t] + sa_bias[n,m]) ----------------
__global__ void spatial_scores_kernel(const float* __restrict__ sa_bias) {
    int b = blockIdx.z;
    int n0 = blockIdx.y * 16, m0 = blockIdx.x * 16;
    __shared__ float sL[16 * 24], sR[16 * 24];
    int tid = threadIdx.y * 16 + threadIdx.x;
    for (int i = tid; i < 384; i += 256) {
        sL[i] = g_lhs_s[(b * 512 + n0 + i / 24) * 24 + i % 24];
        sR[i] = g_rhs_s[(b * 512 + m0 + i / 24) * 24 + i % 24];
    }
    __syncthreads();
    int n = n0 + threadIdx.y, m = m0 + threadIdx.x;
    float s = 0.f;
#pragma unroll
    for (int t = 0; t < 24; t++) s += sL[threadIdx.y * 24 + t] * sR[threadIdx.x * 24 + t];
    float a = 1.f / (1.f + expf(-(s + sa_bias[n * 512 + m])));
    g_attn[((size_t)b * 512 + n) * 512 + m] = a;
}

// ---------------- K8: S[b,n,p] = sum_m sa_proj[n,m] * attn[b,m,p]  (tiled SGEMM) ----------------
__global__ void S_gemm_kernel(const float* __restrict__ proj) {
    int b = blockIdx.z;
    int n0 = blockIdx.y * 64, p0 = blockIdx.x * 64;
    __shared__ float sAT[16][65];
    __shared__ float sB[16][64];
    int tx = threadIdx.x, ty = threadIdx.y;
    int tid = ty * 16 + tx;
    float acc[4][4] = {};
    const float* attb = g_attn + (size_t)b * 512 * 512;
    for (int m0 = 0; m0 < 512; m0 += 16) {
#pragma unroll
        for (int i = 0; i < 4; i++) {
            int e = tid + i * 256;
            int ml = e & 15, nl = e >> 4;
            sAT[ml][nl] = proj[(n0 + nl) * 512 + m0 + ml];
            int r = e >> 6, c2 = e & 63;
            sB[r][c2] = attb[(m0 + r) * 512 + p0 + c2];
        }
        __syncthreads();
#pragma unroll
        for (int mm = 0; mm < 16; mm++) {
            float ra[4], rb[4];
#pragma unroll
            for (int a = 0; a < 4; a++) ra[a] = sAT[mm][ty + 16 * a];
#pragma unroll
            for (int bb = 0; bb < 4; bb++) rb[bb] = sB[mm][tx + 16 * bb];
#pragma unroll
            for (int a = 0; a < 4; a++)
#pragma unroll
                for (int bb = 0; bb < 4; bb++) acc[a][bb] += ra[a] * rb[bb];
        }
        __syncthreads();
    }
    float* Sb = g_S + (size_t)b * 512 * 512;
#pragma unroll
    for (int a = 0; a < 4; a++) {
        int n = n0 + ty + 16 * a;
#pragma unroll
        for (int bb = 0; bb < 4; bb++) Sb[n * 512 + p0 + tx + 16 * bb] = acc[a][bb];
    }
}

// ---------------- K9: spat = softmax over n (column softmax) ----------------
__global__ void spat_softmax_kernel() {
    int idx = blockIdx.x * blockDim.x + threadIdx.x;  // b*512 + p
    if (idx >= B_ * N_) return;
    int b = idx >> 9, p = idx & 511;
    const float* base = g_S + (size_t)b * 262144 + p;
    float* ob = g_spat + (size_t)b * 262144 + p;
    float mx = -1e30f;
    for (int n = 0; n < 512; n++) mx = fmaxf(mx, base[n * 512]);
    float sum = 0.f;
    for (int n = 0; n < 512; n++) {
        float e = expf(base[n * 512] - mx);
        sum += e;
        ob[n * 512] = e;
    }
    float inv = 1.f / sum;
    for (int n = 0; n < 512; n++) ob[n * 512] *= inv;
}

// ---------------- K10: H[(b,k),n,j] = sum_m (cheb[k][m,n]*spat[b,m,n]) * x[b,m,j] ----------------
__global__ void cheb_gemm_kernel(const float* __restrict__ cheb, const float* __restrict__ x) {
    int bz = blockIdx.z;
    int b = bz / 3, k = bz - b * 3;
    int n0 = blockIdx.y * 64, j0 = blockIdx.x * 64;
    __shared__ float sA[16][64];
    __shared__ float sX[16][64];
    int tx = threadIdx.x, ty = threadIdx.y;
    int tid = ty * 16 + tx;
    float acc[4][4] = {};
    const float* chebk = cheb + k * 262144;
    const float* spatb = g_spat + (size_t)b * 262144;
    const float* xb = x + (size_t)b * 512 * 768;
    for (int m0 = 0; m0 < 512; m0 += 16) {
#pragma unroll
        for (int i = 0; i < 4; i++) {
            int e = tid + i * 256;
            int r = e >> 6, c = e & 63;
            int gi = (m0 + r) * 512 + n0 + c;
            sA[r][c] = chebk[gi] * spatb[gi];
            sX[r][c] = xb[(m0 + r) * 768 + j0 + c];
        }
        __syncthreads();
#pragma unroll
        for (int mm = 0; mm < 16; mm++) {
            float ra[4], rb[4];
#pragma unroll
            for (int a = 0; a < 4; a++) ra[a] = sA[mm][ty + 16 * a];
#pragma unroll
            for (int bb = 0; bb < 4; bb++) rb[bb] = sX[mm][tx + 16 * bb];
#pragma unroll
            for (int a = 0; a < 4; a++)
#pragma unroll
                for (int bb = 0; bb < 4; bb++) acc[a][bb] += ra[a] * rb[bb];
        }
        __syncthreads();
    }
    float* Hb = g_H + ((size_t)(b * 3 + k) * 512) * 768;
#pragma unroll
    for (int a = 0; a < 4; a++) {
        int n = n0 + ty + 16 * a;
#pragma unroll
        for (int bb = 0; bb < 4; bb++) Hb[n * 768 + j0 + tx + 16 * bb] = acc[a][bb];
    }
}

// ---------------- K11: fused gcn -> time conv + skip -> relu -> layernorm -> out ----------------
__global__ void final_kernel(const float* __restrict__ x, const float* __restrict__ w_cheb,
                             const float* __restrict__ time_w, const float* __restrict__ time_b,
                             const float* __restrict__ skip_w, const float* __restrict__ skip_b,
                             const float* __restrict__ ln_g, const float* __restrict__ ln_b,
                             float* __restrict__ out) {
    int bn = blockIdx.x;
    int b = bn >> 9, n = bn & 511;
    int tid = threadIdx.x;  // 64
    __shared__ float sH[3 * 32 * 24];
    __shared__ float sx[768];
    __shared__ float sg[64][26];
    __shared__ float sv[64 * 24];
    __shared__ float smu[24], srs[24];

    for (int k = 0; k < 3; k++) {
        const float* src = g_H + ((size_t)(b * 3 + k) * 512 + n) * 768;
        for (int i = tid; i < 768; i += 64) sH[k * 768 + i] = src[i];
    }
    const float* xrow = x + (size_t)bn * 768;
    for (int i = tid; i < 768; i += 64) sx[i] = xrow[i];
    __syncthreads();

    {   // gcn[o][t] = relu(sum_{k,f} H * w_cheb)
        int o = tid;
        float acc[24];
#pragma unroll
        for (int t = 0; t < 24; t++) acc[t] = 0.f;
        for (int kf = 0; kf < 96; kf++) {
            float w = w_cheb[kf * 64 + o];
            const float* hr = &sH[kf * 24];
#pragma unroll
            for (int t = 0; t < 24; t++) acc[t] += hr[t] * w;
        }
        sg[o][0] = 0.f;
        sg[o][25] = 0.f;
#pragma unroll
        for (int t = 0; t < 24; t++) sg[o][t + 1] = fmaxf(acc[t], 0.f);
    }
    __syncthreads();

    {   // v[c][t] = relu(timeconv + skip + biases)
        int c = tid;
        float acc[24];
#pragma unroll
        for (int t = 0; t < 24; t++) acc[t] = 0.f;
        for (int g = 0; g < 64; g++) {
            float w0 = time_w[(c * 64 + g) * 3 + 0];
            float w1 = time_w[(c * 64 + g) * 3 + 1];
            float w2 = time_w[(c * 64 + g) * 3 + 2];
            const float* gr = sg[g];
#pragma unroll
            for (int t = 0; t < 24; t++) acc[t] += gr[t] * w0 + gr[t + 1] * w1 + gr[t + 2] * w2;
        }
        for (int f = 0; f < 32; f++) {
            float w = skip_w[c * 32 + f];
            const float* xr = &sx[f * 24];
#pragma unroll
            for (int t = 0; t < 24; t++) acc[t] += xr[t] * w;
        }
        float bias = time_b[c] + skip_b[c];
#pragma unroll
        for (int t = 0; t < 24; t++) sv[c * 24 + t] = fmaxf(acc[t] + bias, 0.f);
    }
    __syncthreads();

    if (tid < 24) {
        int t = tid;
        float s = 0.f, s2 = 0.f;
        for (int c = 0; c < 64; c++) {
            float v = sv[c * 24 + t];
            s += v;
            s2 += v * v;
        }
        float mu = s * (1.f / 64.f);
        float var = s2 * (1.f / 64.f) - mu * mu;
        smu[t] = mu;
        srs[t] = rsqrtf(var + 1e-5f);
    }
    __syncthreads();

    float* orow = out + (size_t)bn * 1536;
    for (int i = tid; i < 1536; i += 64) {
        int c = i / 24, t = i - c * 24;
        orow[i] = (sv[i] - smu[t]) * srs[t] * ln_g[c] + ln_b[c];
    }
}

// ---------------- launch ----------------
extern "C" void kernel_launch(void* const* d_in, const int* in_sizes, int n_in,
                              void* d_out, int out_size) {
    const float* x       = (const float*)d_in[0];
    const float* cheb    = (const float*)d_in[1];
    const float* w_cheb  = (const float*)d_in[2];
    const float* sa_wa   = (const float*)d_in[3];
    const float* sa_wb   = (const float*)d_in[4];
    const float* sa_wc   = (const float*)d_in[5];
    const float* sa_bias = (const float*)d_in[6];
    const float* sa_proj = (const float*)d_in[7];
    const float* ta_w1   = (const float*)d_in[8];
    const float* ta_w2   = (const float*)d_in[9];
    const float* ta_w3   = (const float*)d_in[10];
    const float* ta_bias = (const float*)d_in[11];
    const float* ta_proj = (const float*)d_in[12];
    const float* time_w  = (const float*)d_in[13];
    const float* time_b  = (const float*)d_in[14];
    const float* skip_w  = (const float*)d_in[15];
    const float* skip_b  = (const float*)d_in[16];
    const float* ln_g    = (const float*)d_in[17];
    const float* ln_b    = (const float*)d_in[18];
    float* out = (float*)d_out;

    // temporal attention
    rhs_t_kernel<<<B_ * N_, 128>>>(x, ta_w3);
    tmp_bt_kernel<<<B_, 768>>>(x, ta_w1);
    lhs_t_kernel<<<(B_ * T_ * N_ + 255) / 256, 256>>>(ta_w2);
    temporal_attn_kernel<<<B_, 576>>>(ta_bias, ta_proj);
    xtemp_kernel<<<(B_ * N_ * F_ * T_ + 255) / 256, 256>>>(x);

    // spatial attention
    spre_kernel<<<B_ * N_, 128>>>(sa_wa, sa_wb, sa_wc);
    spatial_scores_kernel<<<dim3(32, 32, B_), dim3(16, 16)>>>(sa_bias);
    S_gemm_kernel<<<dim3(8, 8, B_), dim3(16, 16)>>>(sa_proj);
    spat_softmax_kernel<<<(B_ * N_ + 255) / 256, 256>>>();

    // chebyshev graph conv (batched over b,k)
    cheb_gemm_kernel<<<dim3(12, 8, B_ * K_), dim3(16, 16)>>>(cheb, x);

    // fused epilogue: gcn matmul + time conv + skip + relu + layernorm
    final_kernel<<<B_ * N_, 64>>>(x, w_cheb, time_w, time_b, skip_w, skip_b, ln_g, ln_b, out);
}

// round 2
// speedup vs baseline: 1.1958x; 1.1958x over previous
#include <cuda_runtime.h>
#include <math.h>

#define B_ 32
#define N_ 512
#define F_ 32
#define T_ 24
#define K_ 3
#define GC_ 64
#define TC_ 64

// ---------------- scratch (device globals; no allocations allowed) ----------------
__device__ float g_rhs_tT[B_ * T_ * N_];         // [b,t,n]  (transposed rhs_t)
__device__ float g_tmp_part[B_ * 8 * 768];       // [b,chunk,ft]
__device__ float g_tmp_bt[B_ * T_ * F_];         // [b,t,f]
__device__ float g_lhs_t[B_ * T_ * N_];          // [b,t,n]
__device__ float g_temp_w[B_ * T_ * T_];         // [b,t,u]
__device__ float g_xtemp[B_ * N_ * F_ * T_];     // [b,n,f,u]
__device__ float g_lhs_s[B_ * N_ * T_];
__device__ float g_rhs_s[B_ * N_ * T_];
__device__ float g_attn[B_ * N_ * N_];           // sigmoid(scores+bias)
__device__ float g_S[B_ * N_ * N_];
__device__ float g_spat[B_ * N_ * N_];
__device__ float g_projT[N_ * N_];               // sa_proj transposed
__device__ float g_H[(size_t)B_ * K_ * N_ * F_ * T_];  // [(b*3+k), n, f*24+t]

// ---------------- K1: rhs_tT[b,t,n] = sum_f ta_w3[f] * x[b,n,f,t] ----------------
__global__ void rhs_t_kernel(const float* __restrict__ x, const float* __restrict__ w3) {
    int bn = blockIdx.x;
    int b = bn >> 9, n = bn & 511;
    __shared__ float row[768];
    const float* xr = x + (size_t)bn * 768;
    for (int i = threadIdx.x; i < 768; i += 128) row[i] = xr[i];
    __syncthreads();
    if (threadIdx.x < 24) {
        int t = threadIdx.x;
        float a = 0.f;
#pragma unroll
        for (int f = 0; f < 32; f++) a += w3[f] * row[f * 24 + t];
        g_rhs_tT[(b * 24 + t) * 512 + n] = a;
    }
}

// ---------------- K2a: partial tmp over n-chunks ----------------
__global__ void tmp_bt_part_kernel(const float* __restrict__ x, const float* __restrict__ w1) {
    int chunk = blockIdx.x;          // 0..7
    int b = blockIdx.y;
    int ft = threadIdx.x;            // 768 threads
    const float* xb = x + (size_t)b * 512 * 768;
    int n0 = chunk * 64;
    float a = 0.f;
    for (int n = n0; n < n0 + 64; n++) a += w1[n] * xb[n * 768 + ft];
    g_tmp_part[(b * 8 + chunk) * 768 + ft] = a;
}

// ---------------- K2b: reduce partials -> g_tmp_bt[b,t,f] ----------------
__global__ void tmp_bt_reduce_kernel() {
    int idx = blockIdx.x * blockDim.x + threadIdx.x;  // 32*768
    if (idx >= B_ * 768) return;
    int b = idx / 768, ft = idx % 768;
    float a = 0.f;
#pragma unroll
    for (int c = 0; c < 8; c++) a += g_tmp_part[(b * 8 + c) * 768 + ft];
    int f = ft / 24, t = ft - f * 24;
    g_tmp_bt[(b * 24 + t) * 32 + f] = a;
}

// ---------------- K3: lhs_t[b,t,n] = sum_f tmp_bt[b,t,f] * ta_w2[f,n] ----------------
__global__ void lhs_t_kernel(const float* __restrict__ w2) {
    int idx = blockIdx.x * blockDim.x + threadIdx.x;
    if (idx >= B_ * T_ * N_) return;
    int n = idx & 511;
    int bt = idx >> 9;
    float a = 0.f;
#pragma unroll
    for (int f = 0; f < 32; f++) a += g_tmp_bt[bt * 32 + f] * w2[f * 512 + n];
    g_lhs_t[idx] = a;
}

// ---------------- K4: prod -> sigmoid -> E -> softmax(s)  (block per b, 576 threads) ----------------
__global__ void temporal_attn_kernel(const float* __restrict__ ta_bias,
                                     const float* __restrict__ ta_proj) {
    int b = blockIdx.x;
    int tid = threadIdx.x;       // 0..575
    int t = tid / 24, u = tid - (tid / 24) * 24;
    __shared__ float sL[24][129];
    __shared__ float sR[24][129];
    __shared__ float ssig[576];
    __shared__ float sE[576];

    float p = 0.f;
    for (int n0 = 0; n0 < 512; n0 += 128) {
        __syncthreads();
        for (int i = tid; i < 24 * 128; i += 576) {
            int tt = i >> 7, nn = i & 127;
            sL[tt][nn] = g_lhs_t[(b * 24 + tt) * 512 + n0 + nn];
            sR[tt][nn] = g_rhs_tT[(b * 24 + tt) * 512 + n0 + nn];
        }
        __syncthreads();
#pragma unroll 8
        for (int nn = 0; nn < 128; nn++) p += sL[t][nn] * sR[u][nn];
    }
    ssig[t * 24 + u] = 1.f / (1.f + expf(-(p + ta_bias[t * 24 + u])));
    __syncthreads();

    int s = t;
    float e = 0.f;
#pragma unroll
    for (int tt = 0; tt < 24; tt++) e += ta_proj[s * 24 + tt] * ssig[tt * 24 + u];
    sE[s * 24 + u] = e;
    __syncthreads();

    float mx = -1e30f;
#pragma unroll
    for (int ss = 0; ss < 24; ss++) mx = fmaxf(mx, sE[ss * 24 + u]);
    float sum = 0.f;
#pragma unroll
    for (int ss = 0; ss < 24; ss++) sum += expf(sE[ss * 24 + u] - mx);
    g_temp_w[b * 576 + s * 24 + u] = expf(e - mx) / sum;
}

// ---------------- K5: x_temp[b,n,f,u] = sum_t x[b,n,f,t] * temp_w[b,t,u] ----------------
__global__ void xtemp_kernel(const float* __restrict__ x) {
    int idx = blockIdx.x * blockDim.x + threadIdx.x;
    if (idx >= B_ * N_ * F_ * T_) return;
    int u = idx % 24;
    int row = idx / 24;              // b*N*F + n*F + f
    int b = row / (512 * 32);
    const float* xr = x + (size_t)row * 24;
    const float* tw = g_temp_w + b * 576;
    float a = 0.f;
#pragma unroll
    for (int t = 0; t < 24; t++) a += xr[t] * tw[t * 24 + u];
    g_xtemp[idx] = a;
}

// ---------------- K6: spatial pre: lhs_s / rhs_s per (b,n) row of x_temp ----------------
__global__ void spre_kernel(const float* __restrict__ wa, const float* __restrict__ wb,
                            const float* __restrict__ wc) {
    int bn = blockIdx.x;
    __shared__ float row[768];
    __shared__ float st2[32];
    const float* xr = g_xtemp + (size_t)bn * 768;
    for (int i = threadIdx.x; i < 768; i += 128) row[i] = xr[i];
    __syncthreads();
    if (threadIdx.x < 32) {
        int f = threadIdx.x;
        float a = 0.f;
#pragma unroll
        for (int t = 0; t < 24; t++) a += row[f * 24 + t] * wa[t];
        st2[f] = a;
    }
    __syncthreads();
    if (threadIdx.x < 24) {
        int t = threadIdx.x;
        float l = 0.f, r = 0.f;
#pragma unroll
        for (int f = 0; f < 32; f++) {
            l += st2[f] * wb[f * 24 + t];
            r += wc[f] * row[f * 24 + t];
        }
        g_lhs_s[bn * 24 + t] = l;
        g_rhs_s[bn * 24 + t] = r;
    }
}

// ---------------- K7: attn[b,n,m] = sigmoid(sum_t lhs_s[b,n,t]*rhs_s[b,m,t] + sa_bias[n,m]) ----------------
__global__ void spatial_scores_kernel(const float* __restrict__ sa_bias) {
    int b = blockIdx.z;
    int n0 = blockIdx.y * 16, m0 = blockIdx.x * 16;
    __shared__ float sL[16 * 24], sR[16 * 24];
    int tid = threadIdx.y * 16 + threadIdx.x;
    for (int i = tid; i < 384; i += 256) {
        sL[i] = g_lhs_s[(b * 512 + n0 + i / 24) * 24 + i % 24];
        sR[i] = g_rhs_s[(b * 512 + m0 + i / 24) * 24 + i % 24];
    }
    __syncthreads();
    int n = n0 + threadIdx.y, m = m0 + threadIdx.x;
    float s = 0.f;
#pragma unroll
    for (int t = 0; t < 24; t++) s += sL[threadIdx.y * 24 + t] * sR[threadIdx.x * 24 + t];
    float a = 1.f / (1.f + expf(-(s + sa_bias[n * 512 + m])));
    g_attn[((size_t)b * 512 + n) * 512 + m] = a;
}

// ---------------- transpose sa_proj -> g_projT ----------------
__global__ void transpose512_kernel(const float* __restrict__ in) {
    __shared__ float tile[32][33];
    int x0 = blockIdx.x * 32, y0 = blockIdx.y * 32;
    tile[threadIdx.y][threadIdx.x] = in[(y0 + threadIdx.y) * 512 + x0 + threadIdx.x];
    __syncthreads();
    g_projT[(x0 + threadIdx.y) * 512 + y0 + threadIdx.x] = tile[threadIdx.x][threadIdx.y];
}

// ---------------- K8: S[b,n,p] = sum_m proj[n,m]*attn[b,m,p] ; A from projT ----------------
// 64(n) x 128(p) tile, BK=16, 256 threads, 4x8 micro
__global__ void S_gemm_kernel() {
    int b = blockIdx.z;
    int n0 = blockIdx.y * 64, p0 = blockIdx.x * 128;
    __shared__ float sA[16][64];
    __shared__ float sB[16][128];
    int tid = threadIdx.x;
    int tx = tid & 15, ty = tid >> 4;
    float acc[4][8] = {};
    const float* attb = g_attn + (size_t)b * 262144;
    int ar = tid >> 4, ac4 = tid & 15;
    int xr = tid >> 5, xc4 = tid & 31;
    for (int m0 = 0; m0 < 512; m0 += 16) {
        {
            float4 v = *(const float4*)(g_projT + (m0 + ar) * 512 + n0 + ac4 * 4);
            *(float4*)&sA[ar][ac4 * 4] = v;
        }
#pragma unroll
        for (int it = 0; it < 2; it++) {
            int r = xr + it * 8;
            float4 v = *(const float4*)(attb + (m0 + r) * 512 + p0 + xc4 * 4);
            *(float4*)&sB[r][xc4 * 4] = v;
        }
        __syncthreads();
#pragma unroll
        for (int mm = 0; mm < 16; mm++) {
            float4 a0 = *(const float4*)&sA[mm][ty * 4];
            float xv[8];
#pragma unroll
            for (int i = 0; i < 8; i++) xv[i] = sB[mm][tx + 16 * i];
#pragma unroll
            for (int i = 0; i < 8; i++) {
                acc[0][i] += a0.x * xv[i];
                acc[1][i] += a0.y * xv[i];
                acc[2][i] += a0.z * xv[i];
                acc[3][i] += a0.w * xv[i];
            }
        }
        __syncthreads();
    }
    float* Sb = g_S + (size_t)b * 262144;
#pragma unroll
    for (int a = 0; a < 4; a++) {
        float* p = Sb + (n0 + ty * 4 + a) * 512 + p0 + tx;
#pragma unroll
        for (int i = 0; i < 8; i++) p[16 * i] = acc[a][i];
    }
}

// ---------------- K9: spat = softmax over n (column softmax) ----------------
__global__ void spat_softmax_kernel() {
    int idx = blockIdx.x * blockDim.x + threadIdx.x;
    if (idx >= B_ * N_) return;
    int b = idx >> 9, p = idx & 511;
    const float* base = g_S + (size_t)b * 262144 + p;
    float* ob = g_spat + (size_t)b * 262144 + p;
    float mx = -1e30f;
    for (int n = 0; n < 512; n++) mx = fmaxf(mx, base[n * 512]);
    float sum = 0.f;
    for (int n = 0; n < 512; n++) {
        float e = expf(base[n * 512] - mx);
        sum += e;
        ob[n * 512] = e;
    }
    float inv = 1.f / sum;
    for (int n = 0; n < 512; n++) ob[n * 512] *= inv;
}

// ---------------- K10: H[(b,k),n,j] = sum_m (cheb[k][m,n]*spat[b,m,n]) * x[b,m,j] ----------------
// k-fused: 64(n) x 128(j) tile, BK=16, 256 threads, per-thread 4x8 micro x 3 k
__global__ void cheb_gemm_kernel(const float* __restrict__ cheb, const float* __restrict__ x) {
    int b = blockIdx.z;
    int n0 = blockIdx.y * 64, j0 = blockIdx.x * 128;
    __shared__ float sA[3][16][64];
    __shared__ float sX[16][128];
    int tid = threadIdx.x;
    int tx = tid & 15, ty = tid >> 4;
    float acc[3][4][8] = {};
    const float* spatb = g_spat + (size_t)b * 262144;
    const float* xb = x + (size_t)b * 393216;
    int ar = tid >> 4, ac4 = tid & 15;
    int xr = tid >> 5, xc4 = tid & 31;
    for (int m0 = 0; m0 < 512; m0 += 16) {
        int gi = (m0 + ar) * 512 + n0 + ac4 * 4;
        float4 s4 = *(const float4*)(spatb + gi);
#pragma unroll
        for (int k = 0; k < 3; k++) {
            float4 c4 = *(const float4*)(cheb + k * 262144 + gi);
            float4 r4;
            r4.x = c4.x * s4.x; r4.y = c4.y * s4.y;
            r4.z = c4.z * s4.z; r4.w = c4.w * s4.w;
            *(float4*)&sA[k][ar][ac4 * 4] = r4;
        }
#pragma unroll
        for (int it = 0; it < 2; it++) {
            int r = xr + it * 8;
            float4 v = *(const float4*)(xb + (m0 + r) * 768 + j0 + xc4 * 4);
            *(float4*)&sX[r][xc4 * 4] = v;
        }
        __syncthreads();
#pragma unroll
        for (int mm = 0; mm < 16; mm++) {
            float4 a0 = *(const float4*)&sA[0][mm][ty * 4];
            float4 a1 = *(const float4*)&sA[1][mm][ty * 4];
            float4 a2 = *(const float4*)&sA[2][mm][ty * 4];
            float xv[8];
#pragma unroll
            for (int i = 0; i < 8; i++) xv[i] = sX[mm][tx + 16 * i];
#pragma unroll
            for (int i = 0; i < 8; i++) {
                acc[0][0][i] += a0.x * xv[i];
                acc[0][1][i] += a0.y * xv[i];
                acc[0][2][i] += a0.z * xv[i];
                acc[0][3][i] += a0.w * xv[i];
                acc[1][0][i] += a1.x * xv[i];
                acc[1][1][i] += a1.y * xv[i];
                acc[1][2][i] += a1.z * xv[i];
                acc[1][3][i] += a1.w * xv[i];
                acc[2][0][i] += a2.x * xv[i];
                acc[2][1][i] += a2.y * xv[i];
                acc[2][2][i] += a2.z * xv[i];
                acc[2][3][i] += a2.w * xv[i];
            }
        }
        __syncthreads();
    }
#pragma unroll
    for (int k = 0; k < 3; k++) {
#pragma unroll
        for (int a = 0; a < 4; a++) {
            float* p = g_H + ((size_t)(b * 3 + k) * 512 + n0 + ty * 4 + a) * 768 + j0 + tx;
#pragma unroll
            for (int i = 0; i < 8; i++) p[16 * i] = acc[k][a][i];
        }
    }
}

// ---------------- K11: fused gcn -> time conv + skip -> relu -> layernorm -> out ----------------
// 128 threads: channel = tid>>1, t-half = tid&1
__global__ void final_kernel(const float* __restrict__ x, const float* __restrict__ w_cheb,
                             const float* __restrict__ time_w, const float* __restrict__ time_b,
                             const float* __restrict__ skip_w, const float* __restrict__ skip_b,
                             const float* __restrict__ ln_g, const float* __restrict__ ln_b,
                             float* __restrict__ out) {
    int bn = blockIdx.x;
    int b = bn >> 9, n = bn & 511;
    int tid = threadIdx.x;  // 128
    int ch = tid >> 1, half = tid & 1;
    int tbase = half * 12;
    __shared__ float sH[3 * 32 * 24];
    __shared__ float sx[768];
    __shared__ float sg[64][26];
    __shared__ float sv[64 * 24];
    __shared__ float smu[24], srs[24];

    for (int k = 0; k < 3; k++) {
        const float* src = g_H + ((size_t)(b * 3 + k) * 512 + n) * 768;
        for (int i = tid; i < 768; i += 128) sH[k * 768 + i] = src[i];
    }
    const float* xrow = x + (size_t)bn * 768;
    for (int i = tid; i < 768; i += 128) sx[i] = xrow[i];
    __syncthreads();

    {   // gcn[o][t] = relu(sum_{k,f} H * w_cheb), each thread does 12 t's
        float acc[12];
#pragma unroll
        for (int t = 0; t < 12; t++) acc[t] = 0.f;
        for (int kf = 0; kf < 96; kf++) {
            float w = w_cheb[kf * 64 + ch];
            const float* hr = &sH[kf * 24 + tbase];
#pragma unroll
            for (int t = 0; t < 12; t++) acc[t] += hr[t] * w;
        }
        if (half == 0) { sg[ch][0] = 0.f; sg[ch][25] = 0.f; }
#pragma unroll
        for (int t = 0; t < 12; t++) sg[ch][tbase + t + 1] = fmaxf(acc[t], 0.f);
    }
    __syncthreads();

    {   // v[c][t] = relu(timeconv + skip + biases)
        float acc[12];
#pragma unroll
        for (int t = 0; t < 12; t++) acc[t] = 0.f;
        for (int g = 0; g < 64; g++) {
            float w0 = time_w[(ch * 64 + g) * 3 + 0];
            float w1 = time_w[(ch * 64 + g) * 3 + 1];
            float w2 = time_w[(ch * 64 + g) * 3 + 2];
            const float* gr = &sg[g][tbase];
#pragma unroll
            for (int t = 0; t < 12; t++) acc[t] += gr[t] * w0 + gr[t + 1] * w1 + gr[t + 2] * w2;
        }
        for (int f = 0; f < 32; f++) {
            float w = skip_w[ch * 32 + f];
            const float* xr = &sx[f * 24 + tbase];
#pragma unroll
            for (int t = 0; t < 12; t++) acc[t] += xr[t] * w;
        }
        float bias = time_b[ch] + skip_b[ch];
#pragma unroll
        for (int t = 0; t < 12; t++) sv[ch * 24 + tbase + t] = fmaxf(acc[t] + bias, 0.f);
    }
    __syncthreads();

    if (tid < 24) {
        int t = tid;
        float s = 0.f, s2 = 0.f;
        for (int c = 0; c < 64; c++) {
            float v = sv[c * 24 + t];
            s += v;
            s2 += v * v;
        }
        float mu = s * (1.f / 64.f);
        float var = s2 * (1.f / 64.f) - mu * mu;
        smu[t] = mu;
        srs[t] = rsqrtf(var + 1e-5f);
    }
    __syncthreads();

    float* orow = out + (size_t)bn * 1536;
    for (int i = tid; i < 1536; i += 128) {
        int c = i / 24, t = i - c * 24;
        orow[i] = (sv[i] - smu[t]) * srs[t] * ln_g[c] + ln_b[c];
    }
}

// ---------------- launch ----------------
extern "C" void kernel_launch(void* const* d_in, const int* in_sizes, int n_in,
                              void* d_out, int out_size) {
    const float* x       = (const float*)d_in[0];
    const float* cheb    = (const float*)d_in[1];
    const float* w_cheb  = (const float*)d_in[2];
    const float* sa_wa   = (const float*)d_in[3];
    const float* sa_wb   = (const float*)d_in[4];
    const float* sa_wc   = (const float*)d_in[5];
    const float* sa_bias = (const float*)d_in[6];
    const float* sa_proj = (const float*)d_in[7];
    const float* ta_w1   = (const float*)d_in[8];
    const float* ta_w2   = (const float*)d_in[9];
    const float* ta_w3   = (const float*)d_in[10];
    const float* ta_bias = (const float*)d_in[11];
    const float* ta_proj = (const float*)d_in[12];
    const float* time_w  = (const float*)d_in[13];
    const float* time_b  = (const float*)d_in[14];
    const float* skip_w  = (const float*)d_in[15];
    const float* skip_b  = (const float*)d_in[16];
    const float* ln_g    = (const float*)d_in[17];
    const float* ln_b    = (const float*)d_in[18];
    float* out = (float*)d_out;

    // temporal attention
    rhs_t_kernel<<<B_ * N_, 128>>>(x, ta_w3);
    tmp_bt_part_kernel<<<dim3(8, B_), 768>>>(x, ta_w1);
    tmp_bt_reduce_kernel<<<(B_ * 768 + 255) / 256, 256>>>();
    lhs_t_kernel<<<(B_ * T_ * N_ + 255) / 256, 256>>>(ta_w2);
    temporal_attn_kernel<<<B_, 576>>>(ta_bias, ta_proj);
    xtemp_kernel<<<(B_ * N_ * F_ * T_ + 255) / 256, 256>>>(x);

    // spatial attention
    transpose512_kernel<<<dim3(16, 16), dim3(32, 32)>>>(sa_proj);
    spre_kernel<<<B_ * N_, 128>>>(sa_wa, sa_wb, sa_wc);
    spatial_scores_kernel<<<dim3(32, 32, B_), dim3(16, 16)>>>(sa_bias);
    S_gemm_kernel<<<dim3(4, 8, B_), 256>>>();
    spat_softmax_kernel<<<(B_ * N_ + 255) / 256, 256>>>();

    // chebyshev graph conv (k-fused, batched over b)
    cheb_gemm_kernel<<<dim3(6, 8, B_), 256>>>(cheb, x);

    // fused epilogue: gcn matmul + time conv + skip + relu + layernorm
    final_kernel<<<B_ * N_, 128>>>(x, w_cheb, time_w, time_b, skip_w, skip_b, ln_g, ln_b, out);
}